// round 7
// baseline (speedup 1.0000x reference)
#include <cuda_runtime.h>
#include <cuda_bf16.h>
#include <math.h>
#include <stdint.h>

// ---------------------------------------------------------------------------
// Problem constants
// ---------------------------------------------------------------------------
#define T_STEPS 96
#define N_NODES 1024
#define G_FEAT  128
#define H_DIM   512
#define E_EDGES 32768
#define D2      56
#define IN_W    64
#define M_ROWS  (T_STEPS * N_NODES)      // 98304
#define FC_K    (N_NODES * G_FEAT)       // 131072

// ---------------------------------------------------------------------------
// Device scratch
// ---------------------------------------------------------------------------
__device__ float g_bufA[T_STEPS * N_NODES * G_FEAT];   // 50.3 MB
__device__ float g_bufB[T_STEPS * N_NODES * G_FEAT];   // 50.3 MB
__device__ float g_dinv[T_STEPS * N_NODES];
__device__ int   g_rowstart[T_STEPS * N_NODES];
__device__ int   g_cnt[T_STEPS * N_NODES];
__device__ int   g_csr[T_STEPS * E_EDGES];
__device__ float g_gacc[T_STEPS * D2];
__device__ float g_pre[T_STEPS * 4 * H_DIM];
__device__ float g_h[2 * H_DIM];
__device__ unsigned g_bar_count;
__device__ unsigned g_bar_gen;
// bf16 split weight buffers, transposed to [N=128][K] K-major
__device__ __nv_bfloat16 g_Bt_hi[128 * 1024];
__device__ __nv_bfloat16 g_Bt_lo[128 * 1024];

__device__ __forceinline__ unsigned bf2_bits(__nv_bfloat162 h) {
    return reinterpret_cast<unsigned&>(h);
}
__device__ __forceinline__ uint32_t smem_u32(const void* p) {
    uint32_t a;
    asm("{ .reg .u64 t; cvta.to.shared.u64 t, %1; cvt.u32.u64 %0, t; }" : "=r"(a) : "l"(p));
    return a;
}
__device__ __forceinline__ void cp_async16(uint32_t saddr, const void* gptr) {
    asm volatile("cp.async.cg.shared.global [%0], [%1], 16;" :: "r"(saddr), "l"(gptr));
}
__device__ __forceinline__ void cp_commit() { asm volatile("cp.async.commit_group;"); }
__device__ __forceinline__ void cp_wait0()  { asm volatile("cp.async.wait_group 0;"); }

// mma.sync m16n8k16 row.col f32.bf16.bf16.f32 (PTX ISA 7.0, works on compute_103)
__device__ __forceinline__ void mma16816(float* d, const uint32_t* a, uint32_t b0, uint32_t b1) {
    asm volatile(
        "mma.sync.aligned.m16n8k16.row.col.f32.bf16.bf16.f32 "
        "{%0,%1,%2,%3}, {%4,%5,%6,%7}, {%8,%9}, {%0,%1,%2,%3};"
        : "+f"(d[0]), "+f"(d[1]), "+f"(d[2]), "+f"(d[3])
        : "r"(a[0]), "r"(a[1]), "r"(a[2]), "r"(a[3]), "r"(b0), "r"(b1));
}

// ---------------------------------------------------------------------------
// K0: zero the fc accumulator
// ---------------------------------------------------------------------------
__global__ void zero_gacc_kernel() {
    int i = blockIdx.x * blockDim.x + threadIdx.x;
    if (i < T_STEPS * D2) g_gacc[i] = 0.0f;
}

// ---------------------------------------------------------------------------
// K-B: convert+transpose weights B[K,128] fp32 -> Bt_hi/Bt_lo [128,K] bf16 split
// ---------------------------------------------------------------------------
__global__ void convertB_kernel(const float* __restrict__ B, int K) {
    int idx = blockIdx.x * blockDim.x + threadIdx.x;     // idx = k*128 + n
    if (idx >= 128 * K) return;
    int n = idx & 127, k = idx >> 7;
    float v = B[idx];
    __nv_bfloat16 h = __float2bfloat16_rn(v);
    __nv_bfloat16 l = __float2bfloat16_rn(v - __bfloat162float(h));
    g_Bt_hi[(size_t)n * K + k] = h;
    g_Bt_lo[(size_t)n * K + k] = l;
}

// ---------------------------------------------------------------------------
// K1: pipelined tensor-core split-bf16 GEMM  C[M,128] = A[M,K] @ B[K,128]
// ---------------------------------------------------------------------------
#define SA 72
#define BUF_BYTES (4 * 128 * SA * 2)     // 73728 per buffer
#define TG_SMEM   (2 * BUF_BYTES)        // 147456

__global__ __launch_bounds__(256, 1)
void tgemm_kernel(const float* __restrict__ A, float* __restrict__ C, int K) {
    extern __shared__ char smem[];

    int tid  = threadIdx.x;
    int wid  = tid >> 5, lane = tid & 31;
    int wm   = wid >> 1, wn = wid & 1;
    int grp  = lane >> 2, t4 = lane & 3;

    float acc[2][8][4];
#pragma unroll
    for (int mi = 0; mi < 2; mi++)
#pragma unroll
        for (int ni = 0; ni < 8; ni++)
#pragma unroll
            for (int q = 0; q < 4; q++) acc[mi][ni][q] = 0.0f;

    const float* Ab = A + (size_t)blockIdx.x * 128 * (size_t)K;
    int nchunks = K >> 6;

    auto sAh = [&](int b) { return (__nv_bfloat16*)(smem + b * BUF_BYTES); };
    auto sAl = [&](int b) { return (__nv_bfloat16*)(smem + b * BUF_BYTES) + 128 * SA; };
    auto sBh = [&](int b) { return (__nv_bfloat16*)(smem + b * BUF_BYTES) + 2 * 128 * SA; };
    auto sBl = [&](int b) { return (__nv_bfloat16*)(smem + b * BUF_BYTES) + 3 * 128 * SA; };
    uint32_t smem_b0 = smem_u32(smem);

    float4 areg[8];

#define LD_A(cidx)                                                            \
    {                                                                         \
        const float* Ac = Ab + (cidx) * 64;                                   \
        _Pragma("unroll")                                                     \
        for (int it = 0; it < 8; it++) {                                      \
            int i = tid + it * 256;                                           \
            int row = i >> 4, k4 = (i & 15) << 2;                             \
            areg[it] = *(const float4*)(Ac + (size_t)row * K + k4);           \
        }                                                                     \
    }

#define CVT_STORE_A(b)                                                        \
    {                                                                         \
        __nv_bfloat16* ah = sAh(b);                                           \
        __nv_bfloat16* al = sAl(b);                                           \
        _Pragma("unroll")                                                     \
        for (int it = 0; it < 8; it++) {                                      \
            int i = tid + it * 256;                                           \
            int row = i >> 4, k4 = (i & 15) << 2;                             \
            float4 v = areg[it];                                              \
            __nv_bfloat162 h01 = __floats2bfloat162_rn(v.x, v.y);             \
            __nv_bfloat162 h23 = __floats2bfloat162_rn(v.z, v.w);             \
            __nv_bfloat162 l01 = __floats2bfloat162_rn(v.x - __low2float(h01), v.y - __high2float(h01)); \
            __nv_bfloat162 l23 = __floats2bfloat162_rn(v.z - __low2float(h23), v.w - __high2float(h23)); \
            *(uint2*)(ah + row * SA + k4) = make_uint2(bf2_bits(h01), bf2_bits(h23)); \
            *(uint2*)(al + row * SA + k4) = make_uint2(bf2_bits(l01), bf2_bits(l23)); \
        }                                                                     \
    }

#define CP_B(cidx, b)                                                         \
    {                                                                         \
        uint32_t dsth = smem_b0 + (b) * BUF_BYTES + 2 * 128 * SA * 2;         \
        uint32_t dstl = smem_b0 + (b) * BUF_BYTES + 3 * 128 * SA * 2;         \
        _Pragma("unroll")                                                     \
        for (int it = 0; it < 4; it++) {                                      \
            int i = tid + it * 256;                                           \
            int n = i >> 3, seg = i & 7;                                      \
            size_t goff = (size_t)n * K + (cidx) * 64 + seg * 8;              \
            cp_async16(dsth + n * SA * 2 + seg * 16, g_Bt_hi + goff);         \
            cp_async16(dstl + n * SA * 2 + seg * 16, g_Bt_lo + goff);         \
        }                                                                     \
        cp_commit();                                                          \
    }

    LD_A(0);
    CP_B(0, 0);
    CVT_STORE_A(0);
    cp_wait0();
    __syncthreads();

    for (int c = 0; c < nchunks; c++) {
        int cur = c & 1, nxt = cur ^ 1;
        bool more = (c + 1 < nchunks);
        if (more) {
            CP_B(c + 1, nxt);
            LD_A(c + 1);
        }

        const __nv_bfloat16* pAh = sAh(cur);
        const __nv_bfloat16* pAl = sAl(cur);
        const __nv_bfloat16* pBh = sBh(cur);
        const __nv_bfloat16* pBl = sBl(cur);
#pragma unroll
        for (int ks = 0; ks < 4; ks++) {
            int col = ks * 16 + t4 * 2;
            uint32_t bh[8][2], bl[8][2];
#pragma unroll
            for (int ni = 0; ni < 8; ni++) {
                int n0 = wn * 64 + ni * 8 + grp;
                bh[ni][0] = *(const uint32_t*)(pBh + n0 * SA + col);
                bh[ni][1] = *(const uint32_t*)(pBh + n0 * SA + col + 8);
                bl[ni][0] = *(const uint32_t*)(pBl + n0 * SA + col);
                bl[ni][1] = *(const uint32_t*)(pBl + n0 * SA + col + 8);
            }
#pragma unroll
            for (int mi = 0; mi < 2; mi++) {
                int r0 = wm * 32 + mi * 16 + grp;
                uint32_t ah[4], al[4];
                ah[0] = *(const uint32_t*)(pAh + r0 * SA + col);
                ah[1] = *(const uint32_t*)(pAh + (r0 + 8) * SA + col);
                ah[2] = *(const uint32_t*)(pAh + r0 * SA + col + 8);
                ah[3] = *(const uint32_t*)(pAh + (r0 + 8) * SA + col + 8);
                al[0] = *(const uint32_t*)(pAl + r0 * SA + col);
                al[1] = *(const uint32_t*)(pAl + (r0 + 8) * SA + col);
                al[2] = *(const uint32_t*)(pAl + r0 * SA + col + 8);
                al[3] = *(const uint32_t*)(pAl + (r0 + 8) * SA + col + 8);
#pragma unroll
                for (int ni = 0; ni < 8; ni++) {
                    mma16816(acc[mi][ni], ah, bh[ni][0], bh[ni][1]);
                    mma16816(acc[mi][ni], ah, bl[ni][0], bl[ni][1]);
                    mma16816(acc[mi][ni], al, bh[ni][0], bh[ni][1]);
                }
            }
        }

        if (more) {
            CVT_STORE_A(nxt);
            cp_wait0();
        }
        __syncthreads();
    }

    float* Cb = C + (size_t)blockIdx.x * 128 * 128;
#pragma unroll
    for (int mi = 0; mi < 2; mi++) {
#pragma unroll
        for (int ni = 0; ni < 8; ni++) {
            int row = wm * 32 + mi * 16 + grp;
            int colc = wn * 64 + ni * 8 + t4 * 2;
            float2 v0 = make_float2(acc[mi][ni][0], acc[mi][ni][1]);
            float2 v1 = make_float2(acc[mi][ni][2], acc[mi][ni][3]);
            *(float2*)(Cb + (size_t)row * 128 + colc)       = v0;
            *(float2*)(Cb + (size_t)(row + 8) * 128 + colc) = v1;
        }
    }
#undef LD_A
#undef CVT_STORE_A
#undef CP_B
}

// ---------------------------------------------------------------------------
// K2: per-timestep CSR build + dinv (dtype of edge_index auto-detected)
// ---------------------------------------------------------------------------
__global__ __launch_bounds__(256)
void build_csr_kernel(const void* __restrict__ ei_raw) {
    __shared__ int cnt[N_NODES];
    __shared__ int rowst[N_NODES];
    __shared__ int cursor[N_NODES];
    __shared__ int is64_s;

    int t = blockIdx.x;
    for (int i = threadIdx.x; i < N_NODES; i += blockDim.x) { cnt[i] = 0; cursor[i] = 0; }
    if (threadIdx.x == 0) {
        const int* p32 = (const int*)ei_raw;
        int is64 = 1;
        for (int i = 1; i < 256; i += 2)
            if (p32[i] != 0) { is64 = 0; break; }
        is64_s = is64;
    }
    __syncthreads();
    int is64 = is64_s;

    const int*       ei32 = (const int*)ei_raw;
    const long long* ei64 = (const long long*)ei_raw;

    if (is64) {
        const long long* dsts = ei64 + (size_t)t * 2 * E_EDGES + E_EDGES;
        for (int e = threadIdx.x; e < E_EDGES; e += blockDim.x)
            atomicAdd(&cnt[(int)dsts[e]], 1);
    } else {
        const int* dsts = ei32 + (size_t)t * 2 * E_EDGES + E_EDGES;
        for (int e = threadIdx.x; e < E_EDGES; e += blockDim.x)
            atomicAdd(&cnt[dsts[e]], 1);
    }
    __syncthreads();

    for (int i = threadIdx.x; i < N_NODES; i += blockDim.x)
        g_dinv[t * N_NODES + i] = rsqrtf((float)(cnt[i] + 1));

    if (threadIdx.x < 32) {
        int lane = threadIdx.x;
        int base = lane * 32;
        int s = 0;
        for (int i = 0; i < 32; i++) { rowst[base + i] = s; s += cnt[base + i]; }
        int v = s;
        for (int off = 1; off < 32; off <<= 1) {
            int n = __shfl_up_sync(0xffffffffu, v, off);
            if (lane >= off) v += n;
        }
        int excl = v - s;
        for (int i = 0; i < 32; i++) rowst[base + i] += excl;
    }
    __syncthreads();

    for (int i = threadIdx.x; i < N_NODES; i += blockDim.x) {
        g_rowstart[t * N_NODES + i] = rowst[i];
        g_cnt[t * N_NODES + i]      = cnt[i];
    }
    if (is64) {
        const long long* srcs = ei64 + (size_t)t * 2 * E_EDGES;
        const long long* dsts = srcs + E_EDGES;
        for (int e = threadIdx.x; e < E_EDGES; e += blockDim.x) {
            int d = (int)dsts[e];
            int p = rowst[d] + atomicAdd(&cursor[d], 1);
            g_csr[(size_t)t * E_EDGES + p] = (int)srcs[e];
        }
    } else {
        const int* srcs = ei32 + (size_t)t * 2 * E_EDGES;
        const int* dsts = srcs + E_EDGES;
        for (int e = threadIdx.x; e < E_EDGES; e += blockDim.x) {
            int d = dsts[e];
            int p = rowst[d] + atomicAdd(&cursor[d], 1);
            g_csr[(size_t)t * E_EDGES + p] = srcs[e];
        }
    }
}

// ---------------------------------------------------------------------------
// K3: GCN conv via CSR gather (one warp per output row)
// ---------------------------------------------------------------------------
__global__ __launch_bounds__(256)
void conv_kernel(const float* __restrict__ in, float* __restrict__ out,
                 const float* __restrict__ bias, int do_relu) {
    int gw   = blockIdx.x * (blockDim.x >> 5) + (threadIdx.x >> 5);
    int lane = threadIdx.x & 31;
    int t = gw >> 10;
    int d = gw & 1023;
    if (t >= T_STEPS) return;

    const float* inT = in + (size_t)t * N_NODES * G_FEAT;
    const float* dv  = g_dinv + t * N_NODES;
    float dvd = dv[d];

    float4 acc = *(const float4*)(inT + (size_t)d * G_FEAT + lane * 4);
    acc.x *= dvd; acc.y *= dvd; acc.z *= dvd; acc.w *= dvd;

    int rs  = g_rowstart[t * N_NODES + d];
    int cnt = g_cnt[t * N_NODES + d];
    const int* srcp = g_csr + (size_t)t * E_EDGES + rs;

    for (int e0 = 0; e0 < cnt; e0 += 32) {
        int myn = min(32, cnt - e0);
        int s = 0; float w = 0.0f;
        if (lane < myn) { s = srcp[e0 + lane]; w = dv[s]; }
#pragma unroll 4
        for (int i = 0; i < myn; i++) {
            int   si = __shfl_sync(0xffffffffu, s, i);
            float wi = __shfl_sync(0xffffffffu, w, i);
            float4 v = *(const float4*)(inT + (size_t)si * G_FEAT + lane * 4);
            acc.x = fmaf(wi, v.x, acc.x);
            acc.y = fmaf(wi, v.y, acc.y);
            acc.z = fmaf(wi, v.z, acc.z);
            acc.w = fmaf(wi, v.w, acc.w);
        }
    }

    float4 b4 = *(const float4*)(bias + lane * 4);
    float4 z;
    z.x = fmaf(dvd, acc.x, b4.x);
    z.y = fmaf(dvd, acc.y, b4.y);
    z.z = fmaf(dvd, acc.z, b4.z);
    z.w = fmaf(dvd, acc.w, b4.w);
    if (do_relu) {
        z.x = fmaxf(z.x, 0.0f); z.y = fmaxf(z.y, 0.0f);
        z.z = fmaxf(z.z, 0.0f); z.w = fmaxf(z.w, 0.0f);
    }
    *(float4*)(out + (size_t)t * N_NODES * G_FEAT + (size_t)d * G_FEAT + lane * 4) = z;
}

// ---------------------------------------------------------------------------
// K6: fc as split-K GEMM: gacc[96,56] += V[96, kslice] @ Wfc[kslice, 56]
// float4 LDS for both operands; Ws transposed to [j][k] with 17x16B stride.
// ---------------------------------------------------------------------------
#define WST 68   // 68 floats = 272 B = 17 * 16 B  (odd multiple of 16B)

__global__ __launch_bounds__(256)
void fc_kernel(const float* __restrict__ V, const float* __restrict__ Wfc) {
    __shared__ float Vs[T_STEPS][64];    // 24 KB
    __shared__ float Wst[D2][WST];       // 15.2 KB  [j][k]

    int kbase0 = blockIdx.x * 512;
    float acc[21];
#pragma unroll
    for (int i = 0; i < 21; i++) acc[i] = 0.0f;

    int tt[21], jj[21];
#pragma unroll
    for (int oi = 0; oi < 21; oi++) {
        int o = threadIdx.x + oi * 256;
        tt[oi] = o / D2;
        jj[oi] = o % D2;
    }

    for (int c = 0; c < 8; c++) {
        int kb = kbase0 + c * 64;
        for (int i = threadIdx.x; i < T_STEPS * 64; i += 256) {
            int t = i >> 6, k = i & 63;
            Vs[t][k] = V[(size_t)t * FC_K + kb + k];
        }
        for (int i = threadIdx.x; i < 64 * D2; i += 256) {
            int k = i / D2, j = i % D2;
            Wst[j][k] = Wfc[(size_t)(kb + k) * D2 + j];
        }
        __syncthreads();
#pragma unroll
        for (int oi = 0; oi < 21; oi++) {
            const float4* vp = (const float4*)&Vs[tt[oi]][0];
            const float4* wp = (const float4*)&Wst[jj[oi]][0];
            float s0 = 0.0f, s1 = 0.0f;
#pragma unroll
            for (int k4 = 0; k4 < 16; k4 += 2) {
                float4 a0 = vp[k4],     b0 = wp[k4];
                float4 a1 = vp[k4 + 1], b1 = wp[k4 + 1];
                s0 = fmaf(a0.x, b0.x, s0); s0 = fmaf(a0.y, b0.y, s0);
                s0 = fmaf(a0.z, b0.z, s0); s0 = fmaf(a0.w, b0.w, s0);
                s1 = fmaf(a1.x, b1.x, s1); s1 = fmaf(a1.y, b1.y, s1);
                s1 = fmaf(a1.z, b1.z, s1); s1 = fmaf(a1.w, b1.w, s1);
            }
            acc[oi] += s0 + s1;
        }
        __syncthreads();
    }
#pragma unroll
    for (int oi = 0; oi < 21; oi++)
        atomicAdd(&g_gacc[threadIdx.x + oi * 256], acc[oi]);
}

// ---------------------------------------------------------------------------
// K7: gate pre-activations
// ---------------------------------------------------------------------------
__global__ __launch_bounds__(512)
void pre_kernel(const float* __restrict__ x, const float* __restrict__ Wx,
                const float* __restrict__ Wg, const float* __restrict__ bias,
                const float* __restrict__ bfc, int gate) {
    int t = blockIdx.x;
    int j = threadIdx.x;
    const float* xt = x + t * IN_W;
    float acc = bias[j];
#pragma unroll
    for (int k = 0; k < IN_W; k++) acc = fmaf(xt[k], Wx[k * H_DIM + j], acc);
#pragma unroll
    for (int k = 0; k < D2; k++) {
        float gk = fmaxf(g_gacc[t * D2 + k] + bfc[k], 0.0f);
        acc = fmaf(gk, Wg[k * H_DIM + j], acc);
    }
    g_pre[t * (4 * H_DIM) + gate * H_DIM + j] = acc;
}

// ---------------------------------------------------------------------------
// K8: sequential LSTM, 32 persistent blocks.
// Thread = (gate, unit, part): warp w has combos [w*8, w*8+8), lane = cl*4+part.
// combo = gate*16 + unit; j = blockIdx.x*16 + unit.  128 weights in registers.
// One __syncthreads per step; 4-part reduce via shfl_xor; pre[t+1] prefetch.
// ---------------------------------------------------------------------------
#define LSTM_BLOCKS 32

__device__ __forceinline__ void grid_barrier() {
    __syncthreads();
    if (threadIdx.x == 0) {
        __threadfence();
        unsigned gen = *(volatile unsigned*)&g_bar_gen;
        if (atomicAdd(&g_bar_count, 1u) == LSTM_BLOCKS - 1u) {
            g_bar_count = 0;
            __threadfence();
            atomicAdd(&g_bar_gen, 1u);
        } else {
            while (*(volatile unsigned*)&g_bar_gen == gen) { }
        }
        __threadfence();
    }
    __syncthreads();
}

__global__ __launch_bounds__(256, 1)
void lstm_kernel(const float* __restrict__ Whi, const float* __restrict__ Whf,
                 const float* __restrict__ Whg, const float* __restrict__ Who,
                 float* __restrict__ out, int out_size) {
    __shared__ float h_s[H_DIM];
    __shared__ float gv_s[64];

    int tid  = threadIdx.x;
    int wid  = tid >> 5, lane = tid & 31;
    int combo = wid * 8 + (lane >> 2);   // 0..63
    int part  = lane & 3;                // 0..3, owns k in [part*128, part*128+128)
    int gate  = combo >> 4;              // 0..3
    int unit  = combo & 15;              // 0..15
    int j     = blockIdx.x * 16 + unit;

    const float* W = (gate == 0) ? Whi : (gate == 1) ? Whf : (gate == 2) ? Whg : Who;
    float wreg[128];
#pragma unroll
    for (int k = 0; k < 128; k++) wreg[k] = W[(size_t)(part * 128 + k) * H_DIM + j];

    float cval = 0.0f;
    float pre_next = g_pre[gate * H_DIM + j];   // t = 0

    for (int t = 0; t < T_STEPS; t++) {
        float v = pre_next;
        if (t > 0) {
            const float* hprev = g_h + ((t + 1) & 1) * H_DIM;
            if (tid < 128) *(float4*)&h_s[tid * 4] = *(const float4*)&hprev[tid * 4];
            __syncthreads();
            const float* hp = &h_s[part * 128];
            float p0 = 0.0f, p1 = 0.0f, p2 = 0.0f, p3 = 0.0f;
#pragma unroll
            for (int k = 0; k < 128; k += 4) {
                p0 = fmaf(hp[k + 0], wreg[k + 0], p0);
                p1 = fmaf(hp[k + 1], wreg[k + 1], p1);
                p2 = fmaf(hp[k + 2], wreg[k + 2], p2);
                p3 = fmaf(hp[k + 3], wreg[k + 3], p3);
            }
            float partial = (p0 + p1) + (p2 + p3);
            partial += __shfl_xor_sync(0xffffffffu, partial, 1);
            partial += __shfl_xor_sync(0xffffffffu, partial, 2);
            v += partial;
        }

        float gval = (gate == 2) ? tanhf(v) : 1.0f / (1.0f + expf(-v));
        if (part == 0) gv_s[combo] = gval;
        __syncthreads();

        if (tid < 16) {
            float iv = gv_s[tid], fv = gv_s[16 + tid], gg = gv_s[32 + tid], ov = gv_s[48 + tid];
            cval = fv * cval + iv * gg;
            float hv = ov * tanhf(cval);
            int jj2 = blockIdx.x * 16 + tid;
            out[t * H_DIM + jj2] = hv;
            g_h[(t & 1) * H_DIM + jj2] = hv;
            if (t == T_STEPS - 1) {
                if (T_STEPS * H_DIM + jj2 < out_size)
                    out[T_STEPS * H_DIM + jj2] = hv;
                if ((T_STEPS + 1) * H_DIM + jj2 < out_size)
                    out[(T_STEPS + 1) * H_DIM + jj2] = cval;
            }
        }
        if (t + 1 < T_STEPS)
            pre_next = g_pre[(t + 1) * (4 * H_DIM) + gate * H_DIM + j];
        grid_barrier();
    }
}

// ---------------------------------------------------------------------------
// Host launcher
// ---------------------------------------------------------------------------
extern "C" void kernel_launch(void* const* d_in, const int* in_sizes, int n_in,
                              void* d_out, int out_size) {
    (void)in_sizes; (void)n_in;
    const float* input   = (const float*)d_in[0];
    const float* x_nodes = (const float*)d_in[1];
    const void*  ei      = d_in[2];
    const float* W1  = (const float*)d_in[3];
    const float* b1  = (const float*)d_in[4];
    const float* W2  = (const float*)d_in[5];
    const float* b2  = (const float*)d_in[6];
    const float* Wfc = (const float*)d_in[7];
    const float* bfc = (const float*)d_in[8];
    const float* W_ii = (const float*)d_in[9];
    const float* W_gi = (const float*)d_in[10];
    const float* W_hi = (const float*)d_in[11];
    const float* b_i  = (const float*)d_in[12];
    const float* W_if = (const float*)d_in[13];
    const float* W_gf = (const float*)d_in[14];
    const float* W_hf = (const float*)d_in[15];
    const float* b_f  = (const float*)d_in[16];
    const float* W_ig = (const float*)d_in[17];
    const float* W_gg = (const float*)d_in[18];
    const float* W_hg = (const float*)d_in[19];
    const float* b_g  = (const float*)d_in[20];
    const float* W_io = (const float*)d_in[21];
    const float* W_go = (const float*)d_in[22];
    const float* W_ho = (const float*)d_in[23];
    const float* b_o  = (const float*)d_in[24];
    float* out = (float*)d_out;

    float *bufA, *bufB;
    cudaGetSymbolAddress((void**)&bufA, g_bufA);
    cudaGetSymbolAddress((void**)&bufB, g_bufB);

    cudaFuncSetAttribute(tgemm_kernel, cudaFuncAttributeMaxDynamicSharedMemorySize, TG_SMEM);

    zero_gacc_kernel<<<(T_STEPS * D2 + 255) / 256, 256>>>();

    // GNN path
    convertB_kernel<<<(128 * 1024 + 255) / 256, 256>>>(W1, 1024);
    build_csr_kernel<<<T_STEPS, 256>>>(ei);
    tgemm_kernel<<<M_ROWS / 128, 256, TG_SMEM>>>(x_nodes, bufA, 1024);   // X @ W1
    conv_kernel<<<M_ROWS / 8, 256>>>(bufA, bufB, b1, 1);                 // relu(conv1)
    convertB_kernel<<<(128 * 128 + 255) / 256, 256>>>(W2, 128);
    tgemm_kernel<<<M_ROWS / 128, 256, TG_SMEM>>>(bufB, bufA, 128);       // @ W2
    conv_kernel<<<M_ROWS / 8, 256>>>(bufA, bufB, b2, 0);                 // conv2
    fc_kernel<<<256, 256>>>(bufB, Wfc);

    // gate pre-activations
    pre_kernel<<<T_STEPS, 512>>>(input, W_ii, W_gi, b_i, bfc, 0);
    pre_kernel<<<T_STEPS, 512>>>(input, W_if, W_gf, b_f, bfc, 1);
    pre_kernel<<<T_STEPS, 512>>>(input, W_ig, W_gg, b_g, bfc, 2);
    pre_kernel<<<T_STEPS, 512>>>(input, W_io, W_go, b_o, bfc, 3);

    // sequential LSTM
    lstm_kernel<<<LSTM_BLOCKS, 256>>>(W_hi, W_hf, W_hg, W_ho, out, out_size);
}

// round 9
// speedup vs baseline: 1.1355x; 1.1355x over previous
#include <cuda_runtime.h>
#include <cuda_bf16.h>
#include <math.h>
#include <stdint.h>

// ---------------------------------------------------------------------------
// Problem constants
// ---------------------------------------------------------------------------
#define T_STEPS 96
#define N_NODES 1024
#define G_FEAT  128
#define H_DIM   512
#define E_EDGES 32768
#define D2      56
#define IN_W    64
#define M_ROWS  (T_STEPS * N_NODES)      // 98304
#define FC_K    (N_NODES * G_FEAT)       // 131072

// ---------------------------------------------------------------------------
// Device scratch
// ---------------------------------------------------------------------------
__device__ float g_bufA[T_STEPS * N_NODES * G_FEAT];   // 50.3 MB
__device__ float g_bufB[T_STEPS * N_NODES * G_FEAT];   // 50.3 MB
__device__ float g_dinv[T_STEPS * N_NODES];
__device__ int   g_rowstart[T_STEPS * N_NODES];
__device__ int   g_cnt[T_STEPS * N_NODES];
__device__ int   g_csr[T_STEPS * E_EDGES];
__device__ float g_gacc[T_STEPS * D2];
__device__ float g_pre[T_STEPS * 4 * H_DIM];
__device__ float g_h[2 * H_DIM];
__device__ unsigned g_bar_count;
__device__ unsigned g_bar_gen;
// bf16 split weight buffers, transposed to [N=128][K] K-major
__device__ __nv_bfloat16 g_Bt_hi[128 * 1024];
__device__ __nv_bfloat16 g_Bt_lo[128 * 1024];

__device__ __forceinline__ unsigned bf2_bits(__nv_bfloat162 h) {
    return reinterpret_cast<unsigned&>(h);
}
__device__ __forceinline__ uint32_t smem_u32(const void* p) {
    uint32_t a;
    asm("{ .reg .u64 t; cvta.to.shared.u64 t, %1; cvt.u32.u64 %0, t; }" : "=r"(a) : "l"(p));
    return a;
}
__device__ __forceinline__ void cp_async16(uint32_t saddr, const void* gptr) {
    asm volatile("cp.async.cg.shared.global [%0], [%1], 16;" :: "r"(saddr), "l"(gptr));
}
__device__ __forceinline__ void cp_commit() { asm volatile("cp.async.commit_group;"); }
__device__ __forceinline__ void cp_wait0()  { asm volatile("cp.async.wait_group 0;"); }

// mma.sync m16n8k16 row.col f32.bf16.bf16.f32 (PTX ISA 7.0, works on compute_103)
__device__ __forceinline__ void mma16816(float* d, const uint32_t* a, uint32_t b0, uint32_t b1) {
    asm volatile(
        "mma.sync.aligned.m16n8k16.row.col.f32.bf16.bf16.f32 "
        "{%0,%1,%2,%3}, {%4,%5,%6,%7}, {%8,%9}, {%0,%1,%2,%3};"
        : "+f"(d[0]), "+f"(d[1]), "+f"(d[2]), "+f"(d[3])
        : "r"(a[0]), "r"(a[1]), "r"(a[2]), "r"(a[3]), "r"(b0), "r"(b1));
}
// ldmatrix m8n8.x4 (sm_75+, baseline PTX)
__device__ __forceinline__ void ldsm_x4(uint32_t saddr, uint32_t* r) {
    asm volatile("ldmatrix.sync.aligned.m8n8.x4.shared.b16 {%0,%1,%2,%3}, [%4];"
                 : "=r"(r[0]), "=r"(r[1]), "=r"(r[2]), "=r"(r[3]) : "r"(saddr));
}

// ---------------------------------------------------------------------------
// K0: zero the fc accumulator
// ---------------------------------------------------------------------------
__global__ void zero_gacc_kernel() {
    int i = blockIdx.x * blockDim.x + threadIdx.x;
    if (i < T_STEPS * D2) g_gacc[i] = 0.0f;
}

// ---------------------------------------------------------------------------
// K-B: convert+transpose weights B[K,128] fp32 -> Bt_hi/Bt_lo [128,K] bf16 split
// ---------------------------------------------------------------------------
__global__ void convertB_kernel(const float* __restrict__ B, int K) {
    int idx = blockIdx.x * blockDim.x + threadIdx.x;     // idx = k*128 + n
    if (idx >= 128 * K) return;
    int n = idx & 127, k = idx >> 7;
    float v = B[idx];
    __nv_bfloat16 h = __float2bfloat16_rn(v);
    __nv_bfloat16 l = __float2bfloat16_rn(v - __bfloat162float(h));
    g_Bt_hi[(size_t)n * K + k] = h;
    g_Bt_lo[(size_t)n * K + k] = l;
}

// ---------------------------------------------------------------------------
// K1: pipelined tensor-core split-bf16 GEMM  C[M,128] = A[M,K] @ B[K,128]
// ldmatrix fragment feeding; double-buffered smem; cp.async for B.
// ---------------------------------------------------------------------------
#define SA 72
#define BUF_BYTES (4 * 128 * SA * 2)     // 73728 per buffer
#define TG_SMEM   (2 * BUF_BYTES)        // 147456

__global__ __launch_bounds__(256, 1)
void tgemm_kernel(const float* __restrict__ A, float* __restrict__ C, int K) {
    extern __shared__ char smem[];

    int tid  = threadIdx.x;
    int wid  = tid >> 5, lane = tid & 31;
    int wm   = wid >> 1, wn = wid & 1;
    int grp  = lane >> 2, t4 = lane & 3;

    float acc[2][8][4];
#pragma unroll
    for (int mi = 0; mi < 2; mi++)
#pragma unroll
        for (int ni = 0; ni < 8; ni++)
#pragma unroll
            for (int q = 0; q < 4; q++) acc[mi][ni][q] = 0.0f;

    const float* Ab = A + (size_t)blockIdx.x * 128 * (size_t)K;
    int nchunks = K >> 6;

    auto sAh = [&](int b) { return (__nv_bfloat16*)(smem + b * BUF_BYTES); };
    auto sAl = [&](int b) { return (__nv_bfloat16*)(smem + b * BUF_BYTES) + 128 * SA; };
    uint32_t smem_b0 = smem_u32(smem);

    // ldmatrix per-lane row/col selectors (bf16-element units)
    int aRow = lane & 15;                 // A: lanes 0-15 -> rows 0-15
    int aCol = (lane >> 4) * 8;           //    lanes 16-31 -> col+8
    int bRow = (lane & 7) + ((lane >> 4) * 8);   // B: m0/m1 rows n0..7, m2/m3 rows n8..15
    int bCol = ((lane >> 3) & 1) * 8;            //    m1/m3 at col+8

    float4 areg[8];

#define LD_A(cidx)                                                            \
    {                                                                         \
        const float* Ac = Ab + (cidx) * 64;                                   \
        _Pragma("unroll")                                                     \
        for (int it = 0; it < 8; it++) {                                      \
            int i = tid + it * 256;                                           \
            int row = i >> 4, k4 = (i & 15) << 2;                             \
            areg[it] = *(const float4*)(Ac + (size_t)row * K + k4);           \
        }                                                                     \
    }

#define CVT_STORE_A(b)                                                        \
    {                                                                         \
        __nv_bfloat16* ah = sAh(b);                                           \
        __nv_bfloat16* al = sAl(b);                                           \
        _Pragma("unroll")                                                     \
        for (int it = 0; it < 8; it++) {                                      \
            int i = tid + it * 256;                                           \
            int row = i >> 4, k4 = (i & 15) << 2;                             \
            float4 v = areg[it];                                              \
            __nv_bfloat162 h01 = __floats2bfloat162_rn(v.x, v.y);             \
            __nv_bfloat162 h23 = __floats2bfloat162_rn(v.z, v.w);             \
            __nv_bfloat162 l01 = __floats2bfloat162_rn(v.x - __low2float(h01), v.y - __high2float(h01)); \
            __nv_bfloat162 l23 = __floats2bfloat162_rn(v.z - __low2float(h23), v.w - __high2float(h23)); \
            *(uint2*)(ah + row * SA + k4) = make_uint2(bf2_bits(h01), bf2_bits(h23)); \
            *(uint2*)(al + row * SA + k4) = make_uint2(bf2_bits(l01), bf2_bits(l23)); \
        }                                                                     \
    }

#define CP_B(cidx, b)                                                         \
    {                                                                         \
        uint32_t dsth = smem_b0 + (b) * BUF_BYTES + 2 * 128 * SA * 2;         \
        uint32_t dstl = smem_b0 + (b) * BUF_BYTES + 3 * 128 * SA * 2;         \
        _Pragma("unroll")                                                     \
        for (int it = 0; it < 4; it++) {                                      \
            int i = tid + it * 256;                                           \
            int n = i >> 3, seg = i & 7;                                      \
            size_t goff = (size_t)n * K + (cidx) * 64 + seg * 8;              \
            cp_async16(dsth + n * SA * 2 + seg * 16, g_Bt_hi + goff);         \
            cp_async16(dstl + n * SA * 2 + seg * 16, g_Bt_lo + goff);         \
        }                                                                     \
        cp_commit();                                                          \
    }

    LD_A(0);
    CP_B(0, 0);
    CVT_STORE_A(0);
    cp_wait0();
    __syncthreads();

    for (int c = 0; c < nchunks; c++) {
        int cur = c & 1, nxt = cur ^ 1;
        bool more = (c + 1 < nchunks);
        if (more) {
            CP_B(c + 1, nxt);
            LD_A(c + 1);
        }

        uint32_t uAh = smem_b0 + cur * BUF_BYTES;
        uint32_t uAl = uAh + 128 * SA * 2;
        uint32_t uBh = uAh + 2 * 128 * SA * 2;
        uint32_t uBl = uAh + 3 * 128 * SA * 2;

#pragma unroll
        for (int ks = 0; ks < 4; ks++) {
            int colb = ks * 16;
            // B fragments: 4 ldmatrix.x4 per precision, each serving 2 ni
            uint32_t bh[8][2], bl[8][2];
#pragma unroll
            for (int nip = 0; nip < 4; nip++) {
                int n0b = wn * 64 + nip * 16;
                uint32_t off = (uint32_t)((n0b + bRow) * SA + colb + bCol) * 2;
                uint32_t rh[4], rl[4];
                ldsm_x4(uBh + off, rh);
                ldsm_x4(uBl + off, rl);
                bh[nip * 2][0] = rh[0]; bh[nip * 2][1] = rh[1];
                bh[nip * 2 + 1][0] = rh[2]; bh[nip * 2 + 1][1] = rh[3];
                bl[nip * 2][0] = rl[0]; bl[nip * 2][1] = rl[1];
                bl[nip * 2 + 1][0] = rl[2]; bl[nip * 2 + 1][1] = rl[3];
            }
#pragma unroll
            for (int mi = 0; mi < 2; mi++) {
                int r0b = wm * 32 + mi * 16;
                uint32_t offA = (uint32_t)((r0b + aRow) * SA + colb + aCol) * 2;
                uint32_t ah[4], al[4];
                ldsm_x4(uAh + offA, ah);
                ldsm_x4(uAl + offA, al);
#pragma unroll
                for (int ni = 0; ni < 8; ni++) {
                    mma16816(acc[mi][ni], ah, bh[ni][0], bh[ni][1]);
                    mma16816(acc[mi][ni], ah, bl[ni][0], bl[ni][1]);
                    mma16816(acc[mi][ni], al, bh[ni][0], bh[ni][1]);
                }
            }
        }

        if (more) {
            CVT_STORE_A(nxt);
            cp_wait0();
        }
        __syncthreads();
    }

    float* Cb = C + (size_t)blockIdx.x * 128 * 128;
#pragma unroll
    for (int mi = 0; mi < 2; mi++) {
#pragma unroll
        for (int ni = 0; ni < 8; ni++) {
            int row = wm * 32 + mi * 16 + grp;
            int colc = wn * 64 + ni * 8 + t4 * 2;
            float2 v0 = make_float2(acc[mi][ni][0], acc[mi][ni][1]);
            float2 v1 = make_float2(acc[mi][ni][2], acc[mi][ni][3]);
            *(float2*)(Cb + (size_t)row * 128 + colc)       = v0;
            *(float2*)(Cb + (size_t)(row + 8) * 128 + colc) = v1;
        }
    }
#undef LD_A
#undef CVT_STORE_A
#undef CP_B
}

// ---------------------------------------------------------------------------
// K2: per-timestep CSR build + dinv (dtype of edge_index auto-detected)
// ---------------------------------------------------------------------------
__global__ __launch_bounds__(256)
void build_csr_kernel(const void* __restrict__ ei_raw) {
    __shared__ int cnt[N_NODES];
    __shared__ int rowst[N_NODES];
    __shared__ int cursor[N_NODES];
    __shared__ int is64_s;

    int t = blockIdx.x;
    for (int i = threadIdx.x; i < N_NODES; i += blockDim.x) { cnt[i] = 0; cursor[i] = 0; }
    if (threadIdx.x == 0) {
        const int* p32 = (const int*)ei_raw;
        int is64 = 1;
        for (int i = 1; i < 256; i += 2)
            if (p32[i] != 0) { is64 = 0; break; }
        is64_s = is64;
    }
    __syncthreads();
    int is64 = is64_s;

    const int*       ei32 = (const int*)ei_raw;
    const long long* ei64 = (const long long*)ei_raw;

    if (is64) {
        const long long* dsts = ei64 + (size_t)t * 2 * E_EDGES + E_EDGES;
        for (int e = threadIdx.x; e < E_EDGES; e += blockDim.x)
            atomicAdd(&cnt[(int)dsts[e]], 1);
    } else {
        const int* dsts = ei32 + (size_t)t * 2 * E_EDGES + E_EDGES;
        for (int e = threadIdx.x; e < E_EDGES; e += blockDim.x)
            atomicAdd(&cnt[dsts[e]], 1);
    }
    __syncthreads();

    for (int i = threadIdx.x; i < N_NODES; i += blockDim.x)
        g_dinv[t * N_NODES + i] = rsqrtf((float)(cnt[i] + 1));

    if (threadIdx.x < 32) {
        int lane = threadIdx.x;
        int base = lane * 32;
        int s = 0;
        for (int i = 0; i < 32; i++) { rowst[base + i] = s; s += cnt[base + i]; }
        int v = s;
        for (int off = 1; off < 32; off <<= 1) {
            int n = __shfl_up_sync(0xffffffffu, v, off);
            if (lane >= off) v += n;
        }
        int excl = v - s;
        for (int i = 0; i < 32; i++) rowst[base + i] += excl;
    }
    __syncthreads();

    for (int i = threadIdx.x; i < N_NODES; i += blockDim.x) {
        g_rowstart[t * N_NODES + i] = rowst[i];
        g_cnt[t * N_NODES + i]      = cnt[i];
    }
    if (is64) {
        const long long* srcs = ei64 + (size_t)t * 2 * E_EDGES;
        const long long* dsts = srcs + E_EDGES;
        for (int e = threadIdx.x; e < E_EDGES; e += blockDim.x) {
            int d = (int)dsts[e];
            int p = rowst[d] + atomicAdd(&cursor[d], 1);
            g_csr[(size_t)t * E_EDGES + p] = (int)srcs[e];
        }
    } else {
        const int* srcs = ei32 + (size_t)t * 2 * E_EDGES;
        const int* dsts = srcs + E_EDGES;
        for (int e = threadIdx.x; e < E_EDGES; e += blockDim.x) {
            int d = dsts[e];
            int p = rowst[d] + atomicAdd(&cursor[d], 1);
            g_csr[(size_t)t * E_EDGES + p] = srcs[e];
        }
    }
}

// ---------------------------------------------------------------------------
// K3: GCN conv via CSR gather (one warp per output row)
// ---------------------------------------------------------------------------
__global__ __launch_bounds__(256)
void conv_kernel(const float* __restrict__ in, float* __restrict__ out,
                 const float* __restrict__ bias, int do_relu) {
    int gw   = blockIdx.x * (blockDim.x >> 5) + (threadIdx.x >> 5);
    int lane = threadIdx.x & 31;
    int t = gw >> 10;
    int d = gw & 1023;
    if (t >= T_STEPS) return;

    const float* inT = in + (size_t)t * N_NODES * G_FEAT;
    const float* dv  = g_dinv + t * N_NODES;
    float dvd = dv[d];

    float4 acc = *(const float4*)(inT + (size_t)d * G_FEAT + lane * 4);
    acc.x *= dvd; acc.y *= dvd; acc.z *= dvd; acc.w *= dvd;

    int rs  = g_rowstart[t * N_NODES + d];
    int cnt = g_cnt[t * N_NODES + d];
    const int* srcp = g_csr + (size_t)t * E_EDGES + rs;

    for (int e0 = 0; e0 < cnt; e0 += 32) {
        int myn = min(32, cnt - e0);
        int s = 0; float w = 0.0f;
        if (lane < myn) { s = srcp[e0 + lane]; w = dv[s]; }
#pragma unroll 4
        for (int i = 0; i < myn; i++) {
            int   si = __shfl_sync(0xffffffffu, s, i);
            float wi = __shfl_sync(0xffffffffu, w, i);
            float4 v = *(const float4*)(inT + (size_t)si * G_FEAT + lane * 4);
            acc.x = fmaf(wi, v.x, acc.x);
            acc.y = fmaf(wi, v.y, acc.y);
            acc.z = fmaf(wi, v.z, acc.z);
            acc.w = fmaf(wi, v.w, acc.w);
        }
    }

    float4 b4 = *(const float4*)(bias + lane * 4);
    float4 z;
    z.x = fmaf(dvd, acc.x, b4.x);
    z.y = fmaf(dvd, acc.y, b4.y);
    z.z = fmaf(dvd, acc.z, b4.z);
    z.w = fmaf(dvd, acc.w, b4.w);
    if (do_relu) {
        z.x = fmaxf(z.x, 0.0f); z.y = fmaxf(z.y, 0.0f);
        z.z = fmaxf(z.z, 0.0f); z.w = fmaxf(z.w, 0.0f);
    }
    *(float4*)(out + (size_t)t * N_NODES * G_FEAT + (size_t)d * G_FEAT + lane * 4) = z;
}

// ---------------------------------------------------------------------------
// K6: fc as split-K GEMM: gacc[96,56] += V[96, kslice] @ Wfc[kslice, 56]
// float4 LDS for both operands; Ws transposed to [j][k] with 17x16B stride.
// ---------------------------------------------------------------------------
#define WST 68   // 68 floats = 272 B = 17 * 16 B

__global__ __launch_bounds__(256)
void fc_kernel(const float* __restrict__ V, const float* __restrict__ Wfc) {
    __shared__ float Vs[T_STEPS][64];    // 24 KB
    __shared__ float Wst[D2][WST];       // 15.2 KB  [j][k]

    int kbase0 = blockIdx.x * 512;
    float acc[21];
#pragma unroll
    for (int i = 0; i < 21; i++) acc[i] = 0.0f;

    int tt[21], jj[21];
#pragma unroll
    for (int oi = 0; oi < 21; oi++) {
        int o = threadIdx.x + oi * 256;
        tt[oi] = o / D2;
        jj[oi] = o % D2;
    }

    for (int c = 0; c < 8; c++) {
        int kb = kbase0 + c * 64;
        for (int i = threadIdx.x; i < T_STEPS * 64; i += 256) {
            int t = i >> 6, k = i & 63;
            Vs[t][k] = V[(size_t)t * FC_K + kb + k];
        }
        for (int i = threadIdx.x; i < 64 * D2; i += 256) {
            int k = i / D2, j = i % D2;
            Wst[j][k] = Wfc[(size_t)(kb + k) * D2 + j];
        }
        __syncthreads();
#pragma unroll
        for (int oi = 0; oi < 21; oi++) {
            const float4* vp = (const float4*)&Vs[tt[oi]][0];
            const float4* wp = (const float4*)&Wst[jj[oi]][0];
            float s0 = 0.0f, s1 = 0.0f;
#pragma unroll
            for (int k4 = 0; k4 < 16; k4 += 2) {
                float4 a0 = vp[k4],     b0 = wp[k4];
                float4 a1 = vp[k4 + 1], b1 = wp[k4 + 1];
                s0 = fmaf(a0.x, b0.x, s0); s0 = fmaf(a0.y, b0.y, s0);
                s0 = fmaf(a0.z, b0.z, s0); s0 = fmaf(a0.w, b0.w, s0);
                s1 = fmaf(a1.x, b1.x, s1); s1 = fmaf(a1.y, b1.y, s1);
                s1 = fmaf(a1.z, b1.z, s1); s1 = fmaf(a1.w, b1.w, s1);
            }
            acc[oi] += s0 + s1;
        }
        __syncthreads();
    }
#pragma unroll
    for (int oi = 0; oi < 21; oi++)
        atomicAdd(&g_gacc[threadIdx.x + oi * 256], acc[oi]);
}

// ---------------------------------------------------------------------------
// K7: gate pre-activations
// ---------------------------------------------------------------------------
__global__ __launch_bounds__(512)
void pre_kernel(const float* __restrict__ x, const float* __restrict__ Wx,
                const float* __restrict__ Wg, const float* __restrict__ bias,
                const float* __restrict__ bfc, int gate) {
    int t = blockIdx.x;
    int j = threadIdx.x;
    const float* xt = x + t * IN_W;
    float acc = bias[j];
#pragma unroll
    for (int k = 0; k < IN_W; k++) acc = fmaf(xt[k], Wx[k * H_DIM + j], acc);
#pragma unroll
    for (int k = 0; k < D2; k++) {
        float gk = fmaxf(g_gacc[t * D2 + k] + bfc[k], 0.0f);
        acc = fmaf(gk, Wg[k * H_DIM + j], acc);
    }
    g_pre[t * (4 * H_DIM) + gate * H_DIM + j] = acc;
}

// ---------------------------------------------------------------------------
// K8: sequential LSTM (round-6 version: 64 blocks, wreg[64], nanosleep spin)
// ---------------------------------------------------------------------------
#define LSTM_BLOCKS 64

__device__ __forceinline__ void grid_barrier() {
    __syncthreads();
    if (threadIdx.x == 0) {
        __threadfence();
        unsigned gen = *(volatile unsigned*)&g_bar_gen;
        if (atomicAdd(&g_bar_count, 1u) == LSTM_BLOCKS - 1u) {
            g_bar_count = 0;
            __threadfence();
            atomicAdd(&g_bar_gen, 1u);
        } else {
            while (*(volatile unsigned*)&g_bar_gen == gen) { __nanosleep(64); }
        }
        __threadfence();
    }
    __syncthreads();
}

__global__ __launch_bounds__(256)
void lstm_kernel(const float* __restrict__ Whi, const float* __restrict__ Whf,
                 const float* __restrict__ Whg, const float* __restrict__ Who,
                 float* __restrict__ out, int out_size) {
    __shared__ float h_s[H_DIM];
    __shared__ float red[8][33];
    __shared__ float gv[32];

    int tid  = threadIdx.x;
    int part = tid >> 5;
    int c    = tid & 31;
    int gate = c >> 3;
    int ul   = c & 7;
    int j    = blockIdx.x * 8 + ul;

    const float* W = (gate == 0) ? Whi : (gate == 1) ? Whf : (gate == 2) ? Whg : Who;
    float wreg[64];
#pragma unroll
    for (int k = 0; k < 64; k++) wreg[k] = W[(size_t)(part * 64 + k) * H_DIM + j];

    float cval = 0.0f;

    for (int t = 0; t < T_STEPS; t++) {
        float partial = 0.0f;
        if (t > 0) {
            const float* hprev = g_h + ((t + 1) & 1) * H_DIM;
            if (tid < 128) *(float4*)&h_s[tid * 4] = *(const float4*)&hprev[tid * 4];
            __syncthreads();
            const float* hp = &h_s[part * 64];
#pragma unroll
            for (int k = 0; k < 64; k++) partial = fmaf(hp[k], wreg[k], partial);
        }
        red[part][c] = partial;
        __syncthreads();
        if (part == 0) {
            float v = g_pre[t * (4 * H_DIM) + gate * H_DIM + j];
#pragma unroll
            for (int p = 0; p < 8; p++) v += red[p][c];
            gv[c] = (gate == 2) ? tanhf(v) : 1.0f / (1.0f + expf(-v));
        }
        __syncthreads();
        if (tid < 8) {
            float iv = gv[tid], fv = gv[8 + tid], gg = gv[16 + tid], ov = gv[24 + tid];
            cval = fv * cval + iv * gg;
            float hv = ov * tanhf(cval);
            int jj = blockIdx.x * 8 + tid;
            out[t * H_DIM + jj] = hv;
            g_h[(t & 1) * H_DIM + jj] = hv;
            if (t == T_STEPS - 1) {
                if (T_STEPS * H_DIM + jj < out_size)
                    out[T_STEPS * H_DIM + jj] = hv;
                if ((T_STEPS + 1) * H_DIM + jj < out_size)
                    out[(T_STEPS + 1) * H_DIM + jj] = cval;
            }
        }
        grid_barrier();
    }
}

// ---------------------------------------------------------------------------
// Host launcher
// ---------------------------------------------------------------------------
extern "C" void kernel_launch(void* const* d_in, const int* in_sizes, int n_in,
                              void* d_out, int out_size) {
    (void)in_sizes; (void)n_in;
    const float* input   = (const float*)d_in[0];
    const float* x_nodes = (const float*)d_in[1];
    const void*  ei      = d_in[2];
    const float* W1  = (const float*)d_in[3];
    const float* b1  = (const float*)d_in[4];
    const float* W2  = (const float*)d_in[5];
    const float* b2  = (const float*)d_in[6];
    const float* Wfc = (const float*)d_in[7];
    const float* bfc = (const float*)d_in[8];
    const float* W_ii = (const float*)d_in[9];
    const float* W_gi = (const float*)d_in[10];
    const float* W_hi = (const float*)d_in[11];
    const float* b_i  = (const float*)d_in[12];
    const float* W_if = (const float*)d_in[13];
    const float* W_gf = (const float*)d_in[14];
    const float* W_hf = (const float*)d_in[15];
    const float* b_f  = (const float*)d_in[16];
    const float* W_ig = (const float*)d_in[17];
    const float* W_gg = (const float*)d_in[18];
    const float* W_hg = (const float*)d_in[19];
    const float* b_g  = (const float*)d_in[20];
    const float* W_io = (const float*)d_in[21];
    const float* W_go = (const float*)d_in[22];
    const float* W_ho = (const float*)d_in[23];
    const float* b_o  = (const float*)d_in[24];
    float* out = (float*)d_out;

    float *bufA, *bufB;
    cudaGetSymbolAddress((void**)&bufA, g_bufA);
    cudaGetSymbolAddress((void**)&bufB, g_bufB);

    cudaFuncSetAttribute(tgemm_kernel, cudaFuncAttributeMaxDynamicSharedMemorySize, TG_SMEM);

    zero_gacc_kernel<<<(T_STEPS * D2 + 255) / 256, 256>>>();

    // GNN path
    convertB_kernel<<<(128 * 1024 + 255) / 256, 256>>>(W1, 1024);
    build_csr_kernel<<<T_STEPS, 256>>>(ei);
    tgemm_kernel<<<M_ROWS / 128, 256, TG_SMEM>>>(x_nodes, bufA, 1024);   // X @ W1
    conv_kernel<<<M_ROWS / 8, 256>>>(bufA, bufB, b1, 1);                 // relu(conv1)
    convertB_kernel<<<(128 * 128 + 255) / 256, 256>>>(W2, 128);
    tgemm_kernel<<<M_ROWS / 128, 256, TG_SMEM>>>(bufB, bufA, 128);       // @ W2
    conv_kernel<<<M_ROWS / 8, 256>>>(bufA, bufB, b2, 0);                 // conv2
    fc_kernel<<<256, 256>>>(bufB, Wfc);

    // gate pre-activations
    pre_kernel<<<T_STEPS, 512>>>(input, W_ii, W_gi, b_i, bfc, 0);
    pre_kernel<<<T_STEPS, 512>>>(input, W_if, W_gf, b_f, bfc, 1);
    pre_kernel<<<T_STEPS, 512>>>(input, W_ig, W_gg, b_g, bfc, 2);
    pre_kernel<<<T_STEPS, 512>>>(input, W_io, W_go, b_o, bfc, 3);

    // sequential LSTM
    lstm_kernel<<<LSTM_BLOCKS, 256>>>(W_hi, W_hf, W_hg, W_ho, out, out_size);
}

// round 10
// speedup vs baseline: 1.1759x; 1.0356x over previous
#include <cuda_runtime.h>
#include <cuda_bf16.h>
#include <math.h>
#include <stdint.h>

// ---------------------------------------------------------------------------
// Problem constants
// ---------------------------------------------------------------------------
#define T_STEPS 96
#define N_NODES 1024
#define G_FEAT  128
#define H_DIM   512
#define E_EDGES 32768
#define D2      56
#define IN_W    64
#define M_ROWS  (T_STEPS * N_NODES)      // 98304
#define FC_K    (N_NODES * G_FEAT)       // 131072

// ---------------------------------------------------------------------------
// Device scratch
// ---------------------------------------------------------------------------
__device__ __nv_bfloat16 g_b16A[M_ROWS * G_FEAT];   // 25.2 MB
__device__ __nv_bfloat16 g_b16B[M_ROWS * G_FEAT];   // 25.2 MB
__device__ float g_dinv[T_STEPS * N_NODES];
__device__ int   g_rowstart[T_STEPS * N_NODES];
__device__ int   g_cnt[T_STEPS * N_NODES];
__device__ int   g_csr[T_STEPS * E_EDGES];
__device__ float g_gacc[T_STEPS * D2];
__device__ float g_pre[T_STEPS * 4 * H_DIM];
__device__ float g_h[2 * H_DIM];
__device__ unsigned g_bar_count;
__device__ unsigned g_bar_gen;
// bf16 split weight buffers, transposed to [N=128][K] K-major
__device__ __nv_bfloat16 g_Bt_hi[128 * 1024];
__device__ __nv_bfloat16 g_Bt_lo[128 * 1024];

__device__ __forceinline__ unsigned bf2_bits(__nv_bfloat162 h) {
    return reinterpret_cast<unsigned&>(h);
}
__device__ __forceinline__ __nv_bfloat162 bits_bf2(unsigned u) {
    return reinterpret_cast<__nv_bfloat162&>(u);
}
__device__ __forceinline__ uint32_t smem_u32(const void* p) {
    uint32_t a;
    asm("{ .reg .u64 t; cvta.to.shared.u64 t, %1; cvt.u32.u64 %0, t; }" : "=r"(a) : "l"(p));
    return a;
}
__device__ __forceinline__ void cp_async16(uint32_t saddr, const void* gptr) {
    asm volatile("cp.async.cg.shared.global [%0], [%1], 16;" :: "r"(saddr), "l"(gptr));
}
__device__ __forceinline__ void cp_commit() { asm volatile("cp.async.commit_group;"); }
__device__ __forceinline__ void cp_wait0()  { asm volatile("cp.async.wait_group 0;"); }

// mma.sync m16n8k16 row.col f32.bf16.bf16.f32 (PTX ISA 7.0, works on compute_103)
__device__ __forceinline__ void mma16816(float* d, const uint32_t* a, uint32_t b0, uint32_t b1) {
    asm volatile(
        "mma.sync.aligned.m16n8k16.row.col.f32.bf16.bf16.f32 "
        "{%0,%1,%2,%3}, {%4,%5,%6,%7}, {%8,%9}, {%0,%1,%2,%3};"
        : "+f"(d[0]), "+f"(d[1]), "+f"(d[2]), "+f"(d[3])
        : "r"(a[0]), "r"(a[1]), "r"(a[2]), "r"(a[3]), "r"(b0), "r"(b1));
}
// ldmatrix m8n8.x4 (sm_75+, baseline PTX)
__device__ __forceinline__ void ldsm_x4(uint32_t saddr, uint32_t* r) {
    asm volatile("ldmatrix.sync.aligned.m8n8.x4.shared.b16 {%0,%1,%2,%3}, [%4];"
                 : "=r"(r[0]), "=r"(r[1]), "=r"(r[2]), "=r"(r[3]) : "r"(saddr));
}

// ---------------------------------------------------------------------------
// K0: zero the fc accumulator
// ---------------------------------------------------------------------------
__global__ void zero_gacc_kernel() {
    int i = blockIdx.x * blockDim.x + threadIdx.x;
    if (i < T_STEPS * D2) g_gacc[i] = 0.0f;
}

// ---------------------------------------------------------------------------
// K-B: convert+transpose weights B[K,128] fp32 -> Bt_hi/Bt_lo [128,K] bf16 split
// ---------------------------------------------------------------------------
__global__ void convertB_kernel(const float* __restrict__ B, int K) {
    int idx = blockIdx.x * blockDim.x + threadIdx.x;     // idx = k*128 + n
    if (idx >= 128 * K) return;
    int n = idx & 127, k = idx >> 7;
    float v = B[idx];
    __nv_bfloat16 h = __float2bfloat16_rn(v);
    __nv_bfloat16 l = __float2bfloat16_rn(v - __bfloat162float(h));
    g_Bt_hi[(size_t)n * K + k] = h;
    g_Bt_lo[(size_t)n * K + k] = l;
}

// ---------------------------------------------------------------------------
// K1: pipelined split-bf16 GEMM (fp32 A)  C16[M,128] = A[M,K] @ B[K,128]
// ---------------------------------------------------------------------------
#define SA 72
#define BUF_BYTES (4 * 128 * SA * 2)     // 73728 per buffer
#define TG_SMEM   (2 * BUF_BYTES)        // 147456

__global__ __launch_bounds__(256, 1)
void tgemm_kernel(const float* __restrict__ A, __nv_bfloat16* __restrict__ C, int K) {
    extern __shared__ char smem[];

    int tid  = threadIdx.x;
    int wid  = tid >> 5, lane = tid & 31;
    int wm   = wid >> 1, wn = wid & 1;
    int grp  = lane >> 2, t4 = lane & 3;

    float acc[2][8][4];
#pragma unroll
    for (int mi = 0; mi < 2; mi++)
#pragma unroll
        for (int ni = 0; ni < 8; ni++)
#pragma unroll
            for (int q = 0; q < 4; q++) acc[mi][ni][q] = 0.0f;

    const float* Ab = A + (size_t)blockIdx.x * 128 * (size_t)K;
    int nchunks = K >> 6;

    auto sAh = [&](int b) { return (__nv_bfloat16*)(smem + b * BUF_BYTES); };
    auto sAl = [&](int b) { return (__nv_bfloat16*)(smem + b * BUF_BYTES) + 128 * SA; };
    uint32_t smem_b0 = smem_u32(smem);

    int aRow = lane & 15;
    int aCol = (lane >> 4) * 8;
    int bRow = (lane & 7) + ((lane >> 4) * 8);
    int bCol = ((lane >> 3) & 1) * 8;

    float4 areg[8];

#define LD_A(cidx)                                                            \
    {                                                                         \
        const float* Ac = Ab + (cidx) * 64;                                   \
        _Pragma("unroll")                                                     \
        for (int it = 0; it < 8; it++) {                                      \
            int i = tid + it * 256;                                           \
            int row = i >> 4, k4 = (i & 15) << 2;                             \
            areg[it] = *(const float4*)(Ac + (size_t)row * K + k4);           \
        }                                                                     \
    }

#define CVT_STORE_A(b)                                                        \
    {                                                                         \
        __nv_bfloat16* ah = sAh(b);                                           \
        __nv_bfloat16* al = sAl(b);                                           \
        _Pragma("unroll")                                                     \
        for (int it = 0; it < 8; it++) {                                      \
            int i = tid + it * 256;                                           \
            int row = i >> 4, k4 = (i & 15) << 2;                             \
            float4 v = areg[it];                                              \
            __nv_bfloat162 h01 = __floats2bfloat162_rn(v.x, v.y);             \
            __nv_bfloat162 h23 = __floats2bfloat162_rn(v.z, v.w);             \
            __nv_bfloat162 l01 = __floats2bfloat162_rn(v.x - __low2float(h01), v.y - __high2float(h01)); \
            __nv_bfloat162 l23 = __floats2bfloat162_rn(v.z - __low2float(h23), v.w - __high2float(h23)); \
            *(uint2*)(ah + row * SA + k4) = make_uint2(bf2_bits(h01), bf2_bits(h23)); \
            *(uint2*)(al + row * SA + k4) = make_uint2(bf2_bits(l01), bf2_bits(l23)); \
        }                                                                     \
    }

#define CP_B(cidx, b)                                                         \
    {                                                                         \
        uint32_t dsth = smem_b0 + (b) * BUF_BYTES + 2 * 128 * SA * 2;         \
        uint32_t dstl = smem_b0 + (b) * BUF_BYTES + 3 * 128 * SA * 2;         \
        _Pragma("unroll")                                                     \
        for (int it = 0; it < 4; it++) {                                      \
            int i = tid + it * 256;                                           \
            int n = i >> 3, seg = i & 7;                                      \
            size_t goff = (size_t)n * K + (cidx) * 64 + seg * 8;              \
            cp_async16(dsth + n * SA * 2 + seg * 16, g_Bt_hi + goff);         \
            cp_async16(dstl + n * SA * 2 + seg * 16, g_Bt_lo + goff);         \
        }                                                                     \
        cp_commit();                                                          \
    }

    LD_A(0);
    CP_B(0, 0);
    CVT_STORE_A(0);
    cp_wait0();
    __syncthreads();

    for (int c = 0; c < nchunks; c++) {
        int cur = c & 1, nxt = cur ^ 1;
        bool more = (c + 1 < nchunks);
        if (more) {
            CP_B(c + 1, nxt);
            LD_A(c + 1);
        }

        uint32_t uAh = smem_b0 + cur * BUF_BYTES;
        uint32_t uAl = uAh + 128 * SA * 2;
        uint32_t uBh = uAh + 2 * 128 * SA * 2;
        uint32_t uBl = uAh + 3 * 128 * SA * 2;

#pragma unroll
        for (int ks = 0; ks < 4; ks++) {
            int colb = ks * 16;
            uint32_t bh[8][2], bl[8][2];
#pragma unroll
            for (int nip = 0; nip < 4; nip++) {
                int n0b = wn * 64 + nip * 16;
                uint32_t off = (uint32_t)((n0b + bRow) * SA + colb + bCol) * 2;
                uint32_t rh[4], rl[4];
                ldsm_x4(uBh + off, rh);
                ldsm_x4(uBl + off, rl);
                bh[nip * 2][0] = rh[0]; bh[nip * 2][1] = rh[1];
                bh[nip * 2 + 1][0] = rh[2]; bh[nip * 2 + 1][1] = rh[3];
                bl[nip * 2][0] = rl[0]; bl[nip * 2][1] = rl[1];
                bl[nip * 2 + 1][0] = rl[2]; bl[nip * 2 + 1][1] = rl[3];
            }
#pragma unroll
            for (int mi = 0; mi < 2; mi++) {
                int r0b = wm * 32 + mi * 16;
                uint32_t offA = (uint32_t)((r0b + aRow) * SA + colb + aCol) * 2;
                uint32_t ah[4], al[4];
                ldsm_x4(uAh + offA, ah);
                ldsm_x4(uAl + offA, al);
#pragma unroll
                for (int ni = 0; ni < 8; ni++) {
                    mma16816(acc[mi][ni], ah, bh[ni][0], bh[ni][1]);
                    mma16816(acc[mi][ni], ah, bl[ni][0], bl[ni][1]);
                    mma16816(acc[mi][ni], al, bh[ni][0], bh[ni][1]);
                }
            }
        }

        if (more) {
            CVT_STORE_A(nxt);
            cp_wait0();
        }
        __syncthreads();
    }

    __nv_bfloat16* Cb = C + (size_t)blockIdx.x * 128 * 128;
#pragma unroll
    for (int mi = 0; mi < 2; mi++) {
#pragma unroll
        for (int ni = 0; ni < 8; ni++) {
            int row = wm * 32 + mi * 16 + grp;
            int colc = wn * 64 + ni * 8 + t4 * 2;
            __nv_bfloat162 v0 = __floats2bfloat162_rn(acc[mi][ni][0], acc[mi][ni][1]);
            __nv_bfloat162 v1 = __floats2bfloat162_rn(acc[mi][ni][2], acc[mi][ni][3]);
            *(unsigned*)(Cb + (size_t)row * 128 + colc)       = bf2_bits(v0);
            *(unsigned*)(Cb + (size_t)(row + 8) * 128 + colc) = bf2_bits(v1);
        }
    }
#undef LD_A
#undef CVT_STORE_A
#undef CP_B
}

// ---------------------------------------------------------------------------
// K1b: GEMM2 — A already exact bf16 (conv output).  2 MMA passes, pure cp.async.
// ---------------------------------------------------------------------------
#define BUF2_BYTES (3 * 128 * SA * 2)    // 55296 per buffer
#define TG2_SMEM   (2 * BUF2_BYTES)      // 110592

__global__ __launch_bounds__(256, 1)
void tgemm2_kernel(const __nv_bfloat16* __restrict__ A, __nv_bfloat16* __restrict__ C, int K) {
    extern __shared__ char smem[];

    int tid  = threadIdx.x;
    int wid  = tid >> 5, lane = tid & 31;
    int wm   = wid >> 1, wn = wid & 1;
    int grp  = lane >> 2, t4 = lane & 3;

    float acc[2][8][4];
#pragma unroll
    for (int mi = 0; mi < 2; mi++)
#pragma unroll
        for (int ni = 0; ni < 8; ni++)
#pragma unroll
            for (int q = 0; q < 4; q++) acc[mi][ni][q] = 0.0f;

    const __nv_bfloat16* Ab = A + (size_t)blockIdx.x * 128 * (size_t)K;
    int nchunks = K >> 6;
    uint32_t smem_b0 = smem_u32(smem);

    int aRow = lane & 15;
    int aCol = (lane >> 4) * 8;
    int bRow = (lane & 7) + ((lane >> 4) * 8);
    int bCol = ((lane >> 3) & 1) * 8;

#define CP_AB2(cidx, b)                                                       \
    {                                                                         \
        uint32_t dsta = smem_b0 + (b) * BUF2_BYTES;                           \
        uint32_t dsth = dsta + 128 * SA * 2;                                  \
        uint32_t dstl = dsta + 2 * 128 * SA * 2;                              \
        _Pragma("unroll")                                                     \
        for (int it = 0; it < 4; it++) {                                      \
            int i = tid + it * 256;                                           \
            int n = i >> 3, seg = i & 7;                                      \
            size_t goffB = (size_t)n * K + (cidx) * 64 + seg * 8;             \
            cp_async16(dsta + n * SA * 2 + seg * 16, Ab + goffB);             \
            cp_async16(dsth + n * SA * 2 + seg * 16, g_Bt_hi + goffB);        \
            cp_async16(dstl + n * SA * 2 + seg * 16, g_Bt_lo + goffB);        \
        }                                                                     \
        cp_commit();                                                          \
    }

    CP_AB2(0, 0);
    cp_wait0();
    __syncthreads();

    for (int c = 0; c < nchunks; c++) {
        int cur = c & 1, nxt = cur ^ 1;
        bool more = (c + 1 < nchunks);
        if (more) CP_AB2(c + 1, nxt);

        uint32_t uA  = smem_b0 + cur * BUF2_BYTES;
        uint32_t uBh = uA + 128 * SA * 2;
        uint32_t uBl = uA + 2 * 128 * SA * 2;

#pragma unroll
        for (int ks = 0; ks < 4; ks++) {
            int colb = ks * 16;
            uint32_t bh[8][2], bl[8][2];
#pragma unroll
            for (int nip = 0; nip < 4; nip++) {
                int n0b = wn * 64 + nip * 16;
                uint32_t off = (uint32_t)((n0b + bRow) * SA + colb + bCol) * 2;
                uint32_t rh[4], rl[4];
                ldsm_x4(uBh + off, rh);
                ldsm_x4(uBl + off, rl);
                bh[nip * 2][0] = rh[0]; bh[nip * 2][1] = rh[1];
                bh[nip * 2 + 1][0] = rh[2]; bh[nip * 2 + 1][1] = rh[3];
                bl[nip * 2][0] = rl[0]; bl[nip * 2][1] = rl[1];
                bl[nip * 2 + 1][0] = rl[2]; bl[nip * 2 + 1][1] = rl[3];
            }
#pragma unroll
            for (int mi = 0; mi < 2; mi++) {
                int r0b = wm * 32 + mi * 16;
                uint32_t offA = (uint32_t)((r0b + aRow) * SA + colb + aCol) * 2;
                uint32_t ah[4];
                ldsm_x4(uA + offA, ah);
#pragma unroll
                for (int ni = 0; ni < 8; ni++) {
                    mma16816(acc[mi][ni], ah, bh[ni][0], bh[ni][1]);
                    mma16816(acc[mi][ni], ah, bl[ni][0], bl[ni][1]);
                }
            }
        }

        if (more) cp_wait0();
        __syncthreads();
    }

    __nv_bfloat16* Cb = C + (size_t)blockIdx.x * 128 * 128;
#pragma unroll
    for (int mi = 0; mi < 2; mi++) {
#pragma unroll
        for (int ni = 0; ni < 8; ni++) {
            int row = wm * 32 + mi * 16 + grp;
            int colc = wn * 64 + ni * 8 + t4 * 2;
            __nv_bfloat162 v0 = __floats2bfloat162_rn(acc[mi][ni][0], acc[mi][ni][1]);
            __nv_bfloat162 v1 = __floats2bfloat162_rn(acc[mi][ni][2], acc[mi][ni][3]);
            *(unsigned*)(Cb + (size_t)row * 128 + colc)       = bf2_bits(v0);
            *(unsigned*)(Cb + (size_t)(row + 8) * 128 + colc) = bf2_bits(v1);
        }
    }
#undef CP_AB2
}

// ---------------------------------------------------------------------------
// K2: per-timestep CSR build + dinv (dtype of edge_index auto-detected)
// ---------------------------------------------------------------------------
__global__ __launch_bounds__(256)
void build_csr_kernel(const void* __restrict__ ei_raw) {
    __shared__ int cnt[N_NODES];
    __shared__ int rowst[N_NODES];
    __shared__ int cursor[N_NODES];
    __shared__ int is64_s;

    int t = blockIdx.x;
    for (int i = threadIdx.x; i < N_NODES; i += blockDim.x) { cnt[i] = 0; cursor[i] = 0; }
    if (threadIdx.x == 0) {
        const int* p32 = (const int*)ei_raw;
        int is64 = 1;
        for (int i = 1; i < 256; i += 2)
            if (p32[i] != 0) { is64 = 0; break; }
        is64_s = is64;
    }
    __syncthreads();
    int is64 = is64_s;

    const int*       ei32 = (const int*)ei_raw;
    const long long* ei64 = (const long long*)ei_raw;

    if (is64) {
        const long long* dsts = ei64 + (size_t)t * 2 * E_EDGES + E_EDGES;
        for (int e = threadIdx.x; e < E_EDGES; e += blockDim.x)
            atomicAdd(&cnt[(int)dsts[e]], 1);
    } else {
        const int* dsts = ei32 + (size_t)t * 2 * E_EDGES + E_EDGES;
        for (int e = threadIdx.x; e < E_EDGES; e += blockDim.x)
            atomicAdd(&cnt[dsts[e]], 1);
    }
    __syncthreads();

    for (int i = threadIdx.x; i < N_NODES; i += blockDim.x)
        g_dinv[t * N_NODES + i] = rsqrtf((float)(cnt[i] + 1));

    if (threadIdx.x < 32) {
        int lane = threadIdx.x;
        int base = lane * 32;
        int s = 0;
        for (int i = 0; i < 32; i++) { rowst[base + i] = s; s += cnt[base + i]; }
        int v = s;
        for (int off = 1; off < 32; off <<= 1) {
            int n = __shfl_up_sync(0xffffffffu, v, off);
            if (lane >= off) v += n;
        }
        int excl = v - s;
        for (int i = 0; i < 32; i++) rowst[base + i] += excl;
    }
    __syncthreads();

    for (int i = threadIdx.x; i < N_NODES; i += blockDim.x) {
        g_rowstart[t * N_NODES + i] = rowst[i];
        g_cnt[t * N_NODES + i]      = cnt[i];
    }
    if (is64) {
        const long long* srcs = ei64 + (size_t)t * 2 * E_EDGES;
        const long long* dsts = srcs + E_EDGES;
        for (int e = threadIdx.x; e < E_EDGES; e += blockDim.x) {
            int d = (int)dsts[e];
            int p = rowst[d] + atomicAdd(&cursor[d], 1);
            g_csr[(size_t)t * E_EDGES + p] = (int)srcs[e];
        }
    } else {
        const int* srcs = ei32 + (size_t)t * 2 * E_EDGES;
        const int* dsts = srcs + E_EDGES;
        for (int e = threadIdx.x; e < E_EDGES; e += blockDim.x) {
            int d = dsts[e];
            int p = rowst[d] + atomicAdd(&cursor[d], 1);
            g_csr[(size_t)t * E_EDGES + p] = srcs[e];
        }
    }
}

// ---------------------------------------------------------------------------
// K3: GCN conv via CSR gather (one warp per output row), bf16 in / bf16 out.
// Accumulation stays fp32.  Lane handles 4 feats = 8 B.
// ---------------------------------------------------------------------------
__global__ __launch_bounds__(256)
void conv_kernel(const __nv_bfloat16* __restrict__ in, __nv_bfloat16* __restrict__ out,
                 const float* __restrict__ bias, int do_relu) {
    int gw   = blockIdx.x * (blockDim.x >> 5) + (threadIdx.x >> 5);
    int lane = threadIdx.x & 31;
    int t = gw >> 10;
    int d = gw & 1023;
    if (t >= T_STEPS) return;

    const __nv_bfloat16* inT = in + (size_t)t * N_NODES * G_FEAT;
    const float* dv  = g_dinv + t * N_NODES;
    float dvd = dv[d];

    uint2 selfr = *(const uint2*)(inT + (size_t)d * G_FEAT + lane * 4);
    __nv_bfloat162 s01 = bits_bf2(selfr.x), s23 = bits_bf2(selfr.y);
    float4 acc;
    acc.x = __low2float(s01) * dvd;
    acc.y = __high2float(s01) * dvd;
    acc.z = __low2float(s23) * dvd;
    acc.w = __high2float(s23) * dvd;

    int rs  = g_rowstart[t * N_NODES + d];
    int cnt = g_cnt[t * N_NODES + d];
    const int* srcp = g_csr + (size_t)t * E_EDGES + rs;

    for (int e0 = 0; e0 < cnt; e0 += 32) {
        int myn = min(32, cnt - e0);
        int s = 0; float w = 0.0f;
        if (lane < myn) { s = srcp[e0 + lane]; w = dv[s]; }
#pragma unroll 4
        for (int i = 0; i < myn; i++) {
            int   si = __shfl_sync(0xffffffffu, s, i);
            float wi = __shfl_sync(0xffffffffu, w, i);
            uint2 raw = *(const uint2*)(inT + (size_t)si * G_FEAT + lane * 4);
            __nv_bfloat162 v01 = bits_bf2(raw.x), v23 = bits_bf2(raw.y);
            acc.x = fmaf(wi, __low2float(v01),  acc.x);
            acc.y = fmaf(wi, __high2float(v01), acc.y);
            acc.z = fmaf(wi, __low2float(v23),  acc.z);
            acc.w = fmaf(wi, __high2float(v23), acc.w);
        }
    }

    float4 b4 = *(const float4*)(bias + lane * 4);
    float4 z;
    z.x = fmaf(dvd, acc.x, b4.x);
    z.y = fmaf(dvd, acc.y, b4.y);
    z.z = fmaf(dvd, acc.z, b4.z);
    z.w = fmaf(dvd, acc.w, b4.w);
    if (do_relu) {
        z.x = fmaxf(z.x, 0.0f); z.y = fmaxf(z.y, 0.0f);
        z.z = fmaxf(z.z, 0.0f); z.w = fmaxf(z.w, 0.0f);
    }
    __nv_bfloat162 o01 = __floats2bfloat162_rn(z.x, z.y);
    __nv_bfloat162 o23 = __floats2bfloat162_rn(z.z, z.w);
    *(uint2*)(out + (size_t)t * N_NODES * G_FEAT + (size_t)d * G_FEAT + lane * 4)
        = make_uint2(bf2_bits(o01), bf2_bits(o23));
}

// ---------------------------------------------------------------------------
// K6: fc as split-K GEMM: gacc[96,56] += V16[96, kslice] @ Wfc[kslice, 56]
// ---------------------------------------------------------------------------
#define WST 68   // 68 floats = 272 B = 17 * 16 B

__global__ __launch_bounds__(256)
void fc_kernel(const __nv_bfloat16* __restrict__ V, const float* __restrict__ Wfc) {
    __shared__ float Vs[T_STEPS][64];    // 24 KB
    __shared__ float Wst[D2][WST];       // 15.2 KB  [j][k]

    int kbase0 = blockIdx.x * 512;
    float acc[21];
#pragma unroll
    for (int i = 0; i < 21; i++) acc[i] = 0.0f;

    int tt[21], jj[21];
#pragma unroll
    for (int oi = 0; oi < 21; oi++) {
        int o = threadIdx.x + oi * 256;
        tt[oi] = o / D2;
        jj[oi] = o % D2;
    }

    for (int c = 0; c < 8; c++) {
        int kb = kbase0 + c * 64;
        for (int i = threadIdx.x; i < T_STEPS * 32; i += 256) {
            int t = i >> 5, k2 = (i & 31) * 2;
            unsigned raw = *(const unsigned*)(V + (size_t)t * FC_K + kb + k2);
            __nv_bfloat162 p = bits_bf2(raw);
            Vs[t][k2]     = __low2float(p);
            Vs[t][k2 + 1] = __high2float(p);
        }
        for (int i = threadIdx.x; i < 64 * D2; i += 256) {
            int k = i / D2, j = i % D2;
            Wst[j][k] = Wfc[(size_t)(kb + k) * D2 + j];
        }
        __syncthreads();
#pragma unroll
        for (int oi = 0; oi < 21; oi++) {
            const float4* vp = (const float4*)&Vs[tt[oi]][0];
            const float4* wp = (const float4*)&Wst[jj[oi]][0];
            float s0 = 0.0f, s1 = 0.0f;
#pragma unroll
            for (int k4 = 0; k4 < 16; k4 += 2) {
                float4 a0 = vp[k4],     b0 = wp[k4];
                float4 a1 = vp[k4 + 1], b1 = wp[k4 + 1];
                s0 = fmaf(a0.x, b0.x, s0); s0 = fmaf(a0.y, b0.y, s0);
                s0 = fmaf(a0.z, b0.z, s0); s0 = fmaf(a0.w, b0.w, s0);
                s1 = fmaf(a1.x, b1.x, s1); s1 = fmaf(a1.y, b1.y, s1);
                s1 = fmaf(a1.z, b1.z, s1); s1 = fmaf(a1.w, b1.w, s1);
            }
            acc[oi] += s0 + s1;
        }
        __syncthreads();
    }
#pragma unroll
    for (int oi = 0; oi < 21; oi++)
        atomicAdd(&g_gacc[threadIdx.x + oi * 256], acc[oi]);
}

// ---------------------------------------------------------------------------
// K7: gate pre-activations
// ---------------------------------------------------------------------------
__global__ __launch_bounds__(512)
void pre_kernel(const float* __restrict__ x, const float* __restrict__ Wx,
                const float* __restrict__ Wg, const float* __restrict__ bias,
                const float* __restrict__ bfc, int gate) {
    int t = blockIdx.x;
    int j = threadIdx.x;
    const float* xt = x + t * IN_W;
    float acc = bias[j];
#pragma unroll
    for (int k = 0; k < IN_W; k++) acc = fmaf(xt[k], Wx[k * H_DIM + j], acc);
#pragma unroll
    for (int k = 0; k < D2; k++) {
        float gk = fmaxf(g_gacc[t * D2 + k] + bfc[k], 0.0f);
        acc = fmaf(gk, Wg[k * H_DIM + j], acc);
    }
    g_pre[t * (4 * H_DIM) + gate * H_DIM + j] = acc;
}

// ---------------------------------------------------------------------------
// K8: sequential LSTM (64 blocks, wreg[64], nanosleep spin) — unchanged
// ---------------------------------------------------------------------------
#define LSTM_BLOCKS 64

__device__ __forceinline__ void grid_barrier() {
    __syncthreads();
    if (threadIdx.x == 0) {
        __threadfence();
        unsigned gen = *(volatile unsigned*)&g_bar_gen;
        if (atomicAdd(&g_bar_count, 1u) == LSTM_BLOCKS - 1u) {
            g_bar_count = 0;
            __threadfence();
            atomicAdd(&g_bar_gen, 1u);
        } else {
            while (*(volatile unsigned*)&g_bar_gen == gen) { __nanosleep(64); }
        }
        __threadfence();
    }
    __syncthreads();
}

__global__ __launch_bounds__(256)
void lstm_kernel(const float* __restrict__ Whi, const float* __restrict__ Whf,
                 const float* __restrict__ Whg, const float* __restrict__ Who,
                 float* __restrict__ out, int out_size) {
    __shared__ float h_s[H_DIM];
    __shared__ float red[8][33];
    __shared__ float gv[32];

    int tid  = threadIdx.x;
    int part = tid >> 5;
    int c    = tid & 31;
    int gate = c >> 3;
    int ul   = c & 7;
    int j    = blockIdx.x * 8 + ul;

    const float* W = (gate == 0) ? Whi : (gate == 1) ? Whf : (gate == 2) ? Whg : Who;
    float wreg[64];
#pragma unroll
    for (int k = 0; k < 64; k++) wreg[k] = W[(size_t)(part * 64 + k) * H_DIM + j];

    float cval = 0.0f;

    for (int t = 0; t < T_STEPS; t++) {
        float partial = 0.0f;
        if (t > 0) {
            const float* hprev = g_h + ((t + 1) & 1) * H_DIM;
            if (tid < 128) *(float4*)&h_s[tid * 4] = *(const float4*)&hprev[tid * 4];
            __syncthreads();
            const float* hp = &h_s[part * 64];
#pragma unroll
            for (int k = 0; k < 64; k++) partial = fmaf(hp[k], wreg[k], partial);
        }
        red[part][c] = partial;
        __syncthreads();
        if (part == 0) {
            float v = g_pre[t * (4 * H_DIM) + gate * H_DIM + j];
#pragma unroll
            for (int p = 0; p < 8; p++) v += red[p][c];
            gv[c] = (gate == 2) ? tanhf(v) : 1.0f / (1.0f + expf(-v));
        }
        __syncthreads();
        if (tid < 8) {
            float iv = gv[tid], fv = gv[8 + tid], gg = gv[16 + tid], ov = gv[24 + tid];
            cval = fv * cval + iv * gg;
            float hv = ov * tanhf(cval);
            int jj = blockIdx.x * 8 + tid;
            out[t * H_DIM + jj] = hv;
            g_h[(t & 1) * H_DIM + jj] = hv;
            if (t == T_STEPS - 1) {
                if (T_STEPS * H_DIM + jj < out_size)
                    out[T_STEPS * H_DIM + jj] = hv;
                if ((T_STEPS + 1) * H_DIM + jj < out_size)
                    out[(T_STEPS + 1) * H_DIM + jj] = cval;
            }
        }
        grid_barrier();
    }
}

// ---------------------------------------------------------------------------
// Host launcher
// ---------------------------------------------------------------------------
extern "C" void kernel_launch(void* const* d_in, const int* in_sizes, int n_in,
                              void* d_out, int out_size) {
    (void)in_sizes; (void)n_in;
    const float* input   = (const float*)d_in[0];
    const float* x_nodes = (const float*)d_in[1];
    const void*  ei      = d_in[2];
    const float* W1  = (const float*)d_in[3];
    const float* b1  = (const float*)d_in[4];
    const float* W2  = (const float*)d_in[5];
    const float* b2  = (const float*)d_in[6];
    const float* Wfc = (const float*)d_in[7];
    const float* bfc = (const float*)d_in[8];
    const float* W_ii = (const float*)d_in[9];
    const float* W_gi = (const float*)d_in[10];
    const float* W_hi = (const float*)d_in[11];
    const float* b_i  = (const float*)d_in[12];
    const float* W_if = (const float*)d_in[13];
    const float* W_gf = (const float*)d_in[14];
    const float* W_hf = (const float*)d_in[15];
    const float* b_f  = (const float*)d_in[16];
    const float* W_ig = (const float*)d_in[17];
    const float* W_gg = (const float*)d_in[18];
    const float* W_hg = (const float*)d_in[19];
    const float* b_g  = (const float*)d_in[20];
    const float* W_io = (const float*)d_in[21];
    const float* W_go = (const float*)d_in[22];
    const float* W_ho = (const float*)d_in[23];
    const float* b_o  = (const float*)d_in[24];
    float* out = (float*)d_out;

    __nv_bfloat16 *buf16A, *buf16B;
    cudaGetSymbolAddress((void**)&buf16A, g_b16A);
    cudaGetSymbolAddress((void**)&buf16B, g_b16B);

    cudaFuncSetAttribute(tgemm_kernel,  cudaFuncAttributeMaxDynamicSharedMemorySize, TG_SMEM);
    cudaFuncSetAttribute(tgemm2_kernel, cudaFuncAttributeMaxDynamicSharedMemorySize, TG2_SMEM);

    zero_gacc_kernel<<<(T_STEPS * D2 + 255) / 256, 256>>>();

    // GNN path (activations in bf16)
    convertB_kernel<<<(128 * 1024 + 255) / 256, 256>>>(W1, 1024);
    build_csr_kernel<<<T_STEPS, 256>>>(ei);
    tgemm_kernel<<<M_ROWS / 128, 256, TG_SMEM>>>(x_nodes, buf16A, 1024);   // X @ W1 -> bf16
    conv_kernel<<<M_ROWS / 8, 256>>>(buf16A, buf16B, b1, 1);               // relu(conv1)
    convertB_kernel<<<(128 * 128 + 255) / 256, 256>>>(W2, 128);
    tgemm2_kernel<<<M_ROWS / 128, 256, TG2_SMEM>>>(buf16B, buf16A, 128);   // @ W2 (bf16 A)
    conv_kernel<<<M_ROWS / 8, 256>>>(buf16A, buf16B, b2, 0);               // conv2
    fc_kernel<<<256, 256>>>(buf16B, Wfc);

    // gate pre-activations
    pre_kernel<<<T_STEPS, 512>>>(input, W_ii, W_gi, b_i, bfc, 0);
    pre_kernel<<<T_STEPS, 512>>>(input, W_if, W_gf, b_f, bfc, 1);
    pre_kernel<<<T_STEPS, 512>>>(input, W_ig, W_gg, b_g, bfc, 2);
    pre_kernel<<<T_STEPS, 512>>>(input, W_io, W_go, b_o, bfc, 3);

    // sequential LSTM
    lstm_kernel<<<LSTM_BLOCKS, 256>>>(W_hi, W_hf, W_hg, W_ho, out, out_size);
}